// round 10
// baseline (speedup 1.0000x reference)
#include <cuda_runtime.h>
#include <cstdint>

#define TT 2048
#define DM 1024
#define MROWS 4096

// Scratch (no cudaMalloc allowed)
__device__ float g_q[MROWS*DM];
__device__ float g_k[MROWS*64];     // reused as kfrag (uint32 tf32 frag layout)
__device__ float g_v[MROWS*64];     // reused as vfrag
__device__ float g_attn[MROWS*DM];

static __device__ __forceinline__ uint32_t f2tf32(float x){
    uint32_t u; asm("cvt.rn.tf32.f32 %0, %1;" : "=r"(u) : "f"(x)); return u;
}
// D += A(m16k8 row) * B(k8n8 col), tf32 inputs, f32 accum
static __device__ __forceinline__ void mma8(float* c, const uint32_t* a, const uint32_t* b){
    asm volatile("mma.sync.aligned.m16n8k8.row.col.f32.tf32.tf32.f32 "
        "{%0,%1,%2,%3}, {%4,%5,%6,%7}, {%8,%9}, {%0,%1,%2,%3};"
        : "+f"(c[0]),"+f"(c[1]),"+f"(c[2]),"+f"(c[3])
        : "r"(a[0]),"r"(a[1]),"r"(a[2]),"r"(a[3]), "r"(b[0]),"r"(b[1]));
}

#define ATS 528
#define BTS 264

// ---------------------------------------------------------------------------
// tf32 mma.sync GEMM + bias.  EPI=0: normal float C store.
// EPI=1: store C as tf32 K-B-frag array (attention GEMM1 operand).
// EPI=2: store C as tf32 V-B-frag array with key permutation (GEMM2 operand).
// Frag array layout (uint32): [b][chunk][keytile][dtile][lane][slot]
//   tile base = (((b*32+chunk)*8+keytile)*8+dtile)*64
//   K: off = (kk*4 + (d&3))*2 + ((d&7)>>2),        kk = key&7
//   V: off = ((d&7)*4 + (kn&3))*2 + (kn>>2),       kn = (kk>>1)+((kk&1)<<2)
// ---------------------------------------------------------------------------
template<int NT, int EPI>
__global__ __launch_bounds__(256, 2) void gemm_mma(
    const float* __restrict__ A, const float* __restrict__ W,
    const float* __restrict__ bias, float* __restrict__ C,
    int M, int N, int K)
{
    extern __shared__ char smem[];
    constexpr int WNT  = NT / 32;
    constexpr int NTT  = NT / 8;
    constexpr int ABUF = 32 * ATS;
    constexpr int BBUF = NTT * 4 * BTS;
    constexpr int NBF4 = NT / 32;

    const int tid = threadIdx.x, lane = tid & 31, wid = tid >> 5;
    const int wm = wid >> 2, wn = wid & 3;
    const int bm = blockIdx.y * 128, bn = blockIdx.x * NT;
    const int NC = K >> 5;

    float4 ar[4], br[NBF4];
    auto ldg = [&](int c){
        const int k0 = c << 5;
        #pragma unroll
        for (int i = 0; i < 4; i++){
            int idx = tid + (i << 8); int r = idx >> 3, c4 = (idx & 7) << 2;
            ar[i] = *(const float4*)(A + (size_t)(bm + r) * K + k0 + c4);
        }
        #pragma unroll
        for (int i = 0; i < NBF4; i++){
            int idx = tid + (i << 8); int kk = idx / (NT >> 2), n4 = (idx % (NT >> 2)) << 2;
            br[i] = *(const float4*)(W + (size_t)(k0 + kk) * N + bn + n4);
        }
    };
    auto sts = [&](int buf){
        char* as = smem + buf * ABUF;
        char* bs = smem + 2 * ABUF + buf * BBUF;
        #pragma unroll
        for (int i = 0; i < 4; i++){
            int idx = tid + (i << 8); int r = idx >> 3, c4 = (idx & 7) << 2;
            int mt = r >> 4, rr = r & 15, g = rr & 7, hi = rr >> 3;
            float v[4] = {ar[i].x, ar[i].y, ar[i].z, ar[i].w};
            #pragma unroll
            for (int j = 0; j < 4; j++){
                int cc = c4 + j, ks = cc >> 3, t = cc & 3, chi = (cc & 7) >> 2;
                *(uint32_t*)(as + (mt*4 + ks) * ATS
                    + (((g << 2) + t) * 4 + hi + (chi << 1)) * 4) = f2tf32(v[j]);
            }
        }
        #pragma unroll
        for (int i = 0; i < NBF4; i++){
            int idx = tid + (i << 8); int kk = idx / (NT >> 2), n4 = (idx % (NT >> 2)) << 2;
            int ks = kk >> 3, slot = (kk & 7) >> 2, kb = kk & 3;
            float v[4] = {br[i].x, br[i].y, br[i].z, br[i].w};
            #pragma unroll
            for (int j = 0; j < 4; j++){
                int n = n4 + j, nt = n >> 3;
                *(uint32_t*)(bs + (ks*NTT + nt) * BTS
                    + ((((n & 7) << 2) + kb) * 2 + slot) * 4) = f2tf32(v[j]);
            }
        }
    };

    float acc[4][WNT][4] = {};
    auto comp = [&](int buf){
        const char* as = smem + buf * ABUF;
        const char* bs = smem + 2 * ABUF + buf * BBUF;
        #pragma unroll
        for (int ks = 0; ks < 4; ks++){
            uint4 af[4]; uint2 bf[WNT];
            #pragma unroll
            for (int mt = 0; mt < 4; mt++)
                af[mt] = *(const uint4*)(as + ((wm*4 + mt)*4 + ks) * ATS + lane * 16);
            #pragma unroll
            for (int nt = 0; nt < WNT; nt++)
                bf[nt] = *(const uint2*)(bs + (ks*NTT + wn*WNT + nt) * BTS + lane * 8);
            #pragma unroll
            for (int mt = 0; mt < 4; mt++)
                #pragma unroll
                for (int nt = 0; nt < WNT; nt++)
                    mma8(acc[mt][nt], (const uint32_t*)&af[mt], (const uint32_t*)&bf[nt]);
        }
    };

    ldg(0); sts(0); __syncthreads();
    for (int c = 0; c < NC; c++){
        if (c + 1 < NC) ldg(c + 1);
        comp(c & 1);
        if (c + 1 < NC) sts((c + 1) & 1);
        __syncthreads();
    }

    const int g = lane >> 2, tt = lane & 3;
    uint32_t* Cf = (uint32_t*)C;
    auto put = [&](int key, int d, float val){
        int bI = key >> 11, rk = key & 2047;
        int base = (((bI*32 + (rk >> 6))*8 + ((rk >> 3) & 7))*8 + (d >> 3)) * 64;
        int kk = rk & 7;
        int off;
        if (EPI == 1) off = (kk*4 + (d & 3))*2 + ((d & 7) >> 2);
        else { int kn = (kk >> 1) + ((kk & 1) << 2); off = ((d & 7)*4 + (kn & 3))*2 + (kn >> 2); }
        Cf[base + off] = f2tf32(val);
    };

    #pragma unroll
    for (int mt = 0; mt < 4; mt++){
        int row = bm + wm*64 + mt*16 + g;
        #pragma unroll
        for (int nt = 0; nt < WNT; nt++){
            int col = bn + (wn*WNT + nt)*8 + (tt << 1);
            float b0 = bias[col], b1 = bias[col + 1];
            if (EPI == 0){
                *(float2*)(C + (size_t)row * N + col) =
                    make_float2(acc[mt][nt][0] + b0, acc[mt][nt][1] + b1);
                *(float2*)(C + (size_t)(row + 8) * N + col) =
                    make_float2(acc[mt][nt][2] + b0, acc[mt][nt][3] + b1);
            } else {
                put(row,     col,     acc[mt][nt][0] + b0);
                put(row,     col + 1, acc[mt][nt][1] + b1);
                put(row + 8, col,     acc[mt][nt][2] + b0);
                put(row + 8, col + 1, acc[mt][nt][3] + b1);
            }
        }
    }
}

// ---------------------------------------------------------------------------
// mma.sync flash-MQA v4: K/V fragments LDG'd directly from pre-formatted
// global frag arrays (written by the K/V projection epilogues).
// No STS, no cvt, and NO __syncthreads in the 32-chunk main loop.
// Warp owns m=32; keys split across 2 warp-groups; P stays in registers.
// SMEM: QF 33792 (reused as O-exchange at the end) + LX 512.
// ---------------------------------------------------------------------------
__global__ __launch_bounds__(256, 2) void attn_mma(
    const float* __restrict__ q, const float* __restrict__ kfragf,
    const float* __restrict__ vfragf, float* __restrict__ out)
{
    extern __shared__ char smem[];
    char* QF = smem;                       // 64 A-tiles x 528B = 33792
    float* OX = (float*)smem;              // [128][66] exchange (after loop)
    float* LX = (float*)(smem + 33792);    // [128]

    const uint32_t* kfrag = (const uint32_t*)kfragf;
    const uint32_t* vfrag = (const uint32_t*)vfragf;

    const int tid = threadIdx.x, lane = tid & 31, wid = tid >> 5;
    const int g = lane >> 2, tt = lane & 3;
    const int grp = wid >> 2;              // key half
    const int mq  = wid & 3;               // row quarter (32 rows)
    const int bi = blockIdx.x;
    const int qt = bi & 15, h = (bi >> 4) & 15, b = bi >> 8;
    const int qbase = b * TT + qt * 128;

    // Stage Q (pre-scaled by 1/8) into A-frag layout: tile (mt*8 + ks)
    #pragma unroll
    for (int i = 0; i < 8; i++){
        int idx = tid + (i << 8); int r = idx >> 4, d4 = (idx & 15) << 2;
        float4 a = *(const float4*)(q + (size_t)(qbase + r) * DM + h*64 + d4);
        int mt = r >> 4, rr = r & 15, gg = rr & 7, hi = rr >> 3;
        float vv[4] = {a.x, a.y, a.z, a.w};
        #pragma unroll
        for (int j = 0; j < 4; j++){
            int c = d4 + j, ks = c >> 3, t = c & 3, chi = (c & 7) >> 2;
            *(uint32_t*)(QF + (mt*8 + ks) * ATS
                + (((gg << 2) + t) * 4 + hi + (chi << 1)) * 4) = f2tf32(vv[j] * 0.125f);
        }
    }
    __syncthreads();

    float o[2][8][4] = {};
    float l[2][2] = {};

    for (int c = 0; c < 32; c++){
        // per-chunk frag bases (uint2 units, lane folded in)
        const uint2* kc_ = (const uint2*)(kfrag + (size_t)(b*32 + c) * 4096) + lane;
        const uint2* vc_ = (const uint2*)(vfrag + (size_t)(b*32 + c) * 4096) + lane;

        // GEMM1: S(32 x 32 keys) = Q * K^T ; K-frags straight from L1/L2
        float s[2][4][4] = {};
        #pragma unroll
        for (int ks = 0; ks < 8; ks++){
            uint4 af0 = *(const uint4*)(QF + ((mq*2 + 0)*8 + ks) * ATS + lane * 16);
            uint4 af1 = *(const uint4*)(QF + ((mq*2 + 1)*8 + ks) * ATS + lane * 16);
            #pragma unroll
            for (int nt = 0; nt < 4; nt++){
                uint2 bf = kc_[((grp*4 + nt)*8 + ks) * 32];
                mma8(s[0][nt], (const uint32_t*)&af0, (const uint32_t*)&bf);
                mma8(s[1][nt], (const uint32_t*)&af1, (const uint32_t*)&bf);
            }
        }

        // exp (tf32-rounded so l matches GEMM2 exactly) + partial row sums
        #pragma unroll
        for (int m = 0; m < 2; m++)
            #pragma unroll
            for (int nt = 0; nt < 4; nt++){
                #pragma unroll
                for (int e = 0; e < 4; e++)
                    s[m][nt][e] = __uint_as_float(f2tf32(__expf(s[m][nt][e])));
                l[m][0] += s[m][nt][0] + s[m][nt][1];
                l[m][1] += s[m][nt][2] + s[m][nt][3];
            }

        // GEMM2: O += P * V ; P from registers, V-frags straight from L1/L2
        #pragma unroll
        for (int ksk = 0; ksk < 4; ksk++){
            uint32_t a0[4] = {__float_as_uint(s[0][ksk][0]), __float_as_uint(s[0][ksk][2]),
                              __float_as_uint(s[0][ksk][1]), __float_as_uint(s[0][ksk][3])};
            uint32_t a1[4] = {__float_as_uint(s[1][ksk][0]), __float_as_uint(s[1][ksk][2]),
                              __float_as_uint(s[1][ksk][1]), __float_as_uint(s[1][ksk][3])};
            #pragma unroll
            for (int ntd = 0; ntd < 8; ntd++){
                uint2 bf = vc_[((grp*4 + ksk)*8 + ntd) * 32];
                mma8(o[0][ntd], a0, (const uint32_t*)&bf);
                mma8(o[1][ntd], a1, (const uint32_t*)&bf);
            }
        }
    }

    // quad reduction of partial row sums (lanes sharing g)
    #pragma unroll
    for (int m = 0; m < 2; m++){
        l[m][0] += __shfl_xor_sync(~0u, l[m][0], 1);
        l[m][0] += __shfl_xor_sync(~0u, l[m][0], 2);
        l[m][1] += __shfl_xor_sync(~0u, l[m][1], 1);
        l[m][1] += __shfl_xor_sync(~0u, l[m][1], 2);
    }

    __syncthreads();   // all warps done with QF before it becomes OX

    // cross-group combine: group 1 dumps partial O/l; group 0 sums + stores
    if (grp == 1){
        #pragma unroll
        for (int mt = 0; mt < 2; mt++){
            int r = mq*32 + mt*16 + g;
            #pragma unroll
            for (int ntd = 0; ntd < 8; ntd++){
                int cw = ntd*8 + (tt << 1);
                *(float2*)&OX[r*66 + cw]     = make_float2(o[mt][ntd][0], o[mt][ntd][1]);
                *(float2*)&OX[(r+8)*66 + cw] = make_float2(o[mt][ntd][2], o[mt][ntd][3]);
            }
            if (tt == 0){ LX[r] = l[mt][0]; LX[r+8] = l[mt][1]; }
        }
    }
    __syncthreads();
    if (grp == 0){
        #pragma unroll
        for (int mt = 0; mt < 2; mt++){
            int r = mq*32 + mt*16 + g;
            float ia = 1.f / (l[mt][0] + LX[r]);
            float ib = 1.f / (l[mt][1] + LX[r+8]);
            #pragma unroll
            for (int ntd = 0; ntd < 8; ntd++){
                int cw = ntd*8 + (tt << 1);
                float2 pa = *(const float2*)&OX[r*66 + cw];
                float2 pb = *(const float2*)&OX[(r+8)*66 + cw];
                int col = h*64 + cw;
                *(float2*)(out + (size_t)(qbase + r) * DM + col) =
                    make_float2((o[mt][ntd][0] + pa.x) * ia, (o[mt][ntd][1] + pa.y) * ia);
                *(float2*)(out + (size_t)(qbase + r + 8) * DM + col) =
                    make_float2((o[mt][ntd][2] + pb.x) * ib, (o[mt][ntd][3] + pb.y) * ib);
            }
        }
    }
}

// ---------------------------------------------------------------------------
extern "C" void kernel_launch(void* const* d_in, const int* in_sizes, int n_in,
                              void* d_out, int out_size)
{
    const float* query = (const float*)d_in[0];
    const float* Wq    = (const float*)d_in[1];
    const float* bq    = (const float*)d_in[2];
    const float* Wk    = (const float*)d_in[3];
    const float* bk    = (const float*)d_in[4];
    const float* Wv    = (const float*)d_in[5];
    const float* bv    = (const float*)d_in[6];
    const float* Wo    = (const float*)d_in[7];
    const float* bo    = (const float*)d_in[8];
    float* out = (float*)d_out;

    float *qb, *kb, *vb, *ab;
    cudaGetSymbolAddress((void**)&qb, g_q);
    cudaGetSymbolAddress((void**)&kb, g_k);
    cudaGetSymbolAddress((void**)&vb, g_v);
    cudaGetSymbolAddress((void**)&ab, g_attn);

    const int GS128 = 2*(32*ATS) + 2*(64*BTS);   // 67584
    const int GS64  = 2*(32*ATS) + 2*(32*BTS);   // 50688
    const int ASMEM = 33792 + 512;               // QF/OX + LX

    cudaFuncSetAttribute((const void*)gemm_mma<128,0>, cudaFuncAttributeMaxDynamicSharedMemorySize, GS128);
    cudaFuncSetAttribute((const void*)gemm_mma<64,1>,  cudaFuncAttributeMaxDynamicSharedMemorySize, GS64);
    cudaFuncSetAttribute((const void*)gemm_mma<64,2>,  cudaFuncAttributeMaxDynamicSharedMemorySize, GS64);
    cudaFuncSetAttribute((const void*)attn_mma,        cudaFuncAttributeMaxDynamicSharedMemorySize, ASMEM);

    // K/V projections -> tf32 frag arrays (attention-ready layout)
    gemm_mma<64,1><<<dim3(1, 32), 256, GS64 >>>(query, Wk, bk, kb, MROWS, 64, DM);
    gemm_mma<64,2><<<dim3(1, 32), 256, GS64 >>>(query, Wv, bv, vb, MROWS, 64, DM);
    gemm_mma<128,0><<<dim3(8, 32), 256, GS128>>>(query, Wq, bq, qb, MROWS, DM, DM);

    attn_mma<<<512, 256, ASMEM>>>(qb, kb, vb, ab);

    gemm_mma<128,0><<<dim3(8, 32), 256, GS128>>>(ab, Wo, bo, out, MROWS, DM, DM);
}

// round 12
// speedup vs baseline: 1.5989x; 1.5989x over previous
#include <cuda_runtime.h>
#include <cstdint>

#define TT 2048
#define DM 1024
#define MROWS 4096

// Scratch (no cudaMalloc allowed)
__device__ float g_q[MROWS*DM];
__device__ float g_k[MROWS*64];     // kfrag: tf32 B-frag layout (uint32)
__device__ float g_v[MROWS*64];     // vfrag: tf32 B-frag layout, key-permuted
__device__ float g_attn[MROWS*DM];

static __device__ __forceinline__ uint32_t f2tf32(float x){
    uint32_t u; asm("cvt.rn.tf32.f32 %0, %1;" : "=r"(u) : "f"(x)); return u;
}
// D += A(m16k8 row) * B(k8n8 col), tf32 inputs, f32 accum
static __device__ __forceinline__ void mma8(float* c, const uint32_t* a, const uint32_t* b){
    asm volatile("mma.sync.aligned.m16n8k8.row.col.f32.tf32.tf32.f32 "
        "{%0,%1,%2,%3}, {%4,%5,%6,%7}, {%8,%9}, {%0,%1,%2,%3};"
        : "+f"(c[0]),"+f"(c[1]),"+f"(c[2]),"+f"(c[3])
        : "r"(a[0]),"r"(a[1]),"r"(a[2]),"r"(a[3]), "r"(b[0]),"r"(b[1]));
}
static __device__ __forceinline__ void cp16(uint32_t dst_smem, const void* src){
    asm volatile("cp.async.cg.shared.global [%0], [%1], 16;" :: "r"(dst_smem), "l"(src));
}
static __device__ __forceinline__ uint32_t smem_u32(const void* p){
    uint32_t a;
    asm("{ .reg .u64 t; cvta.to.shared.u64 t, %1; cvt.u32.u64 %0, t; }" : "=r"(a) : "l"(p));
    return a;
}

#define ATS 528
#define BTS 264

// ---------------------------------------------------------------------------
// tf32 mma.sync GEMM + bias.  EPI=0: normal float C store.
// EPI=1: C as tf32 K-B-frag array.  EPI=2: C as tf32 V-B-frag (key-permuted).
// Frag array: tile base = (((b*32+chunk)*8+keytile)*8+dtile)*64 uint32
// ---------------------------------------------------------------------------
template<int NT, int EPI>
__global__ __launch_bounds__(256, 2) void gemm_mma(
    const float* __restrict__ A, const float* __restrict__ W,
    const float* __restrict__ bias, float* __restrict__ C,
    int M, int N, int K)
{
    extern __shared__ char smem[];
    constexpr int WNT  = NT / 32;
    constexpr int NTT  = NT / 8;
    constexpr int ABUF = 32 * ATS;
    constexpr int BBUF = NTT * 4 * BTS;
    constexpr int NBF4 = NT / 32;

    const int tid = threadIdx.x, lane = tid & 31, wid = tid >> 5;
    const int wm = wid >> 2, wn = wid & 3;
    const int bm = blockIdx.y * 128, bn = blockIdx.x * NT;
    const int NC = K >> 5;

    float4 ar[4], br[NBF4];
    auto ldg = [&](int c){
        const int k0 = c << 5;
        #pragma unroll
        for (int i = 0; i < 4; i++){
            int idx = tid + (i << 8); int r = idx >> 3, c4 = (idx & 7) << 2;
            ar[i] = *(const float4*)(A + (size_t)(bm + r) * K + k0 + c4);
        }
        #pragma unroll
        for (int i = 0; i < NBF4; i++){
            int idx = tid + (i << 8); int kk = idx / (NT >> 2), n4 = (idx % (NT >> 2)) << 2;
            br[i] = *(const float4*)(W + (size_t)(k0 + kk) * N + bn + n4);
        }
    };
    auto sts = [&](int buf){
        char* as = smem + buf * ABUF;
        char* bs = smem + 2 * ABUF + buf * BBUF;
        #pragma unroll
        for (int i = 0; i < 4; i++){
            int idx = tid + (i << 8); int r = idx >> 3, c4 = (idx & 7) << 2;
            int mt = r >> 4, rr = r & 15, g = rr & 7, hi = rr >> 3;
            float v[4] = {ar[i].x, ar[i].y, ar[i].z, ar[i].w};
            #pragma unroll
            for (int j = 0; j < 4; j++){
                int cc = c4 + j, ks = cc >> 3, t = cc & 3, chi = (cc & 7) >> 2;
                *(uint32_t*)(as + (mt*4 + ks) * ATS
                    + (((g << 2) + t) * 4 + hi + (chi << 1)) * 4) = f2tf32(v[j]);
            }
        }
        #pragma unroll
        for (int i = 0; i < NBF4; i++){
            int idx = tid + (i << 8); int kk = idx / (NT >> 2), n4 = (idx % (NT >> 2)) << 2;
            int ks = kk >> 3, slot = (kk & 7) >> 2, kb = kk & 3;
            float v[4] = {br[i].x, br[i].y, br[i].z, br[i].w};
            #pragma unroll
            for (int j = 0; j < 4; j++){
                int n = n4 + j, nt = n >> 3;
                *(uint32_t*)(bs + (ks*NTT + nt) * BTS
                    + ((((n & 7) << 2) + kb) * 2 + slot) * 4) = f2tf32(v[j]);
            }
        }
    };

    float acc[4][WNT][4] = {};
    auto comp = [&](int buf){
        const char* as = smem + buf * ABUF;
        const char* bs = smem + 2 * ABUF + buf * BBUF;
        #pragma unroll
        for (int ks = 0; ks < 4; ks++){
            uint4 af[4]; uint2 bf[WNT];
            #pragma unroll
            for (int mt = 0; mt < 4; mt++)
                af[mt] = *(const uint4*)(as + ((wm*4 + mt)*4 + ks) * ATS + lane * 16);
            #pragma unroll
            for (int nt = 0; nt < WNT; nt++)
                bf[nt] = *(const uint2*)(bs + (ks*NTT + wn*WNT + nt) * BTS + lane * 8);
            #pragma unroll
            for (int mt = 0; mt < 4; mt++)
                #pragma unroll
                for (int nt = 0; nt < WNT; nt++)
                    mma8(acc[mt][nt], (const uint32_t*)&af[mt], (const uint32_t*)&bf[nt]);
        }
    };

    ldg(0); sts(0); __syncthreads();
    for (int c = 0; c < NC; c++){
        if (c + 1 < NC) ldg(c + 1);
        comp(c & 1);
        if (c + 1 < NC) sts((c + 1) & 1);
        __syncthreads();
    }

    const int g = lane >> 2, tt = lane & 3;
    uint32_t* Cf = (uint32_t*)C;
    auto put = [&](int key, int d, float val){
        int bI = key >> 11, rk = key & 2047;
        int base = (((bI*32 + (rk >> 6))*8 + ((rk >> 3) & 7))*8 + (d >> 3)) * 64;
        int kk = rk & 7;
        int off;
        if (EPI == 1) off = (kk*4 + (d & 3))*2 + ((d & 7) >> 2);
        else { int kn = (kk >> 1) + ((kk & 1) << 2); off = ((d & 7)*4 + (kn & 3))*2 + (kn >> 2); }
        Cf[base + off] = f2tf32(val);
    };

    #pragma unroll
    for (int mt = 0; mt < 4; mt++){
        int row = bm + wm*64 + mt*16 + g;
        #pragma unroll
        for (int nt = 0; nt < WNT; nt++){
            int col = bn + (wn*WNT + nt)*8 + (tt << 1);
            float b0 = bias[col], b1 = bias[col + 1];
            if (EPI == 0){
                *(float2*)(C + (size_t)row * N + col) =
                    make_float2(acc[mt][nt][0] + b0, acc[mt][nt][1] + b1);
                *(float2*)(C + (size_t)(row + 8) * N + col) =
                    make_float2(acc[mt][nt][2] + b0, acc[mt][nt][3] + b1);
            } else {
                put(row,     col,     acc[mt][nt][0] + b0);
                put(row,     col + 1, acc[mt][nt][1] + b1);
                put(row + 8, col,     acc[mt][nt][2] + b0);
                put(row + 8, col + 1, acc[mt][nt][3] + b1);
            }
        }
    }
}

// ---------------------------------------------------------------------------
// mma.sync flash-MQA v5: pre-formatted K/V frag chunks pulled into SMEM with
// cp.async (contiguous 16B, no cvt, no scatter, no staging regs), then R8-style
// LDS fragment loads. Double-buffered, one __syncthreads per chunk.
// Warp owns m=32; keys split across 2 warp-groups; P stays in registers.
// SMEM: QF 33792 | LX 512 | KF/VF 4x16384 = 99840 -> 2 CTA/SM.
// ---------------------------------------------------------------------------
__global__ __launch_bounds__(256, 2) void attn_mma(
    const float* __restrict__ q, const float* __restrict__ kfragf,
    const float* __restrict__ vfragf, float* __restrict__ out)
{
    extern __shared__ char smem[];
    char* QF = smem;                       // 64 A-tiles x 528B = 33792
    float* OX = (float*)smem;              // [128][66] exchange (after loop)
    float* LX = (float*)(smem + 33792);    // [128]
    char* KB  = smem + 34304;              // KF0|KF1|VF0|VF1, 16384 each

    const uint32_t* kfrag = (const uint32_t*)kfragf;
    const uint32_t* vfrag = (const uint32_t*)vfragf;

    const int tid = threadIdx.x, lane = tid & 31, wid = tid >> 5;
    const int g = lane >> 2, tt = lane & 3;
    const int grp = wid >> 2;              // key half
    const int mq  = wid & 3;               // row quarter (32 rows)
    const int bi = blockIdx.x;
    const int qt = bi & 15, h = (bi >> 4) & 15, b = bi >> 8;
    const int qbase = b * TT + qt * 128;

    const uint32_t KBu = smem_u32(KB);

    // async copy of chunk c's K+V frag data (16KB each) into buffer buf
    auto cpa = [&](int c, int buf){
        const uint32_t* ks = kfrag + (size_t)(b*32 + c) * 4096;
        const uint32_t* vs = vfrag + (size_t)(b*32 + c) * 4096;
        uint32_t kd = KBu + buf * 16384;
        uint32_t vd = KBu + 32768 + buf * 16384;
        #pragma unroll
        for (int j = 0; j < 4; j++){
            int idx = tid + (j << 8);          // 0..1023 float4 units
            cp16(kd + idx * 16, ks + idx * 4);
            cp16(vd + idx * 16, vs + idx * 4);
        }
        asm volatile("cp.async.commit_group;" ::: "memory");
    };

    // Stage Q (pre-scaled by 1/8) into A-frag layout: tile (mt*8 + ks)
    cpa(0, 0);
    #pragma unroll
    for (int i = 0; i < 8; i++){
        int idx = tid + (i << 8); int r = idx >> 4, d4 = (idx & 15) << 2;
        float4 a = *(const float4*)(q + (size_t)(qbase + r) * DM + h*64 + d4);
        int mt = r >> 4, rr = r & 15, gg = rr & 7, hi = rr >> 3;
        float vv[4] = {a.x, a.y, a.z, a.w};
        #pragma unroll
        for (int j = 0; j < 4; j++){
            int c = d4 + j, ks = c >> 3, t = c & 3, chi = (c & 7) >> 2;
            *(uint32_t*)(QF + (mt*8 + ks) * ATS
                + (((gg << 2) + t) * 4 + hi + (chi << 1)) * 4) = f2tf32(vv[j] * 0.125f);
        }
    }
    asm volatile("cp.async.wait_group 0;" ::: "memory");
    __syncthreads();

    float o[2][8][4] = {};
    float l[2][2] = {};

    for (int c = 0; c < 32; c++){
        if (c + 1 < 32) cpa(c + 1, (c + 1) & 1);   // overlaps compute below

        const char* KF = KB + (c & 1) * 16384;
        const char* VF = KB + 32768 + (c & 1) * 16384;

        // GEMM1: S(32 x 32 keys) = Q * K^T ; B-frag shared by both m-tiles
        float s[2][4][4] = {};
        #pragma unroll
        for (int ks = 0; ks < 8; ks++){
            uint4 af0 = *(const uint4*)(QF + ((mq*2 + 0)*8 + ks) * ATS + lane * 16);
            uint4 af1 = *(const uint4*)(QF + ((mq*2 + 1)*8 + ks) * ATS + lane * 16);
            #pragma unroll
            for (int nt = 0; nt < 4; nt++){
                uint2 bf = *(const uint2*)(KF + (((grp*4 + nt)*8 + ks) << 8) + lane * 8);
                mma8(s[0][nt], (const uint32_t*)&af0, (const uint32_t*)&bf);
                mma8(s[1][nt], (const uint32_t*)&af1, (const uint32_t*)&bf);
            }
        }

        // exp (tf32-rounded so l matches GEMM2 exactly) + partial row sums
        #pragma unroll
        for (int m = 0; m < 2; m++)
            #pragma unroll
            for (int nt = 0; nt < 4; nt++){
                #pragma unroll
                for (int e = 0; e < 4; e++)
                    s[m][nt][e] = __uint_as_float(f2tf32(__expf(s[m][nt][e])));
                l[m][0] += s[m][nt][0] + s[m][nt][1];
                l[m][1] += s[m][nt][2] + s[m][nt][3];
            }

        // GEMM2: O += P * V ; P from registers (C-frag -> A-frag reorder)
        #pragma unroll
        for (int ksk = 0; ksk < 4; ksk++){
            uint32_t a0[4] = {__float_as_uint(s[0][ksk][0]), __float_as_uint(s[0][ksk][2]),
                              __float_as_uint(s[0][ksk][1]), __float_as_uint(s[0][ksk][3])};
            uint32_t a1[4] = {__float_as_uint(s[1][ksk][0]), __float_as_uint(s[1][ksk][2]),
                              __float_as_uint(s[1][ksk][1]), __float_as_uint(s[1][ksk][3])};
            #pragma unroll
            for (int ntd = 0; ntd < 8; ntd++){
                uint2 bf = *(const uint2*)(VF + (((grp*4 + ksk)*8 + ntd) << 8) + lane * 8);
                mma8(o[0][ntd], a0, (const uint32_t*)&bf);
                mma8(o[1][ntd], a1, (const uint32_t*)&bf);
            }
        }

        if (c + 1 < 32)
            asm volatile("cp.async.wait_group 0;" ::: "memory");
        __syncthreads();
    }

    // quad reduction of partial row sums (lanes sharing g)
    #pragma unroll
    for (int m = 0; m < 2; m++){
        l[m][0] += __shfl_xor_sync(~0u, l[m][0], 1);
        l[m][0] += __shfl_xor_sync(~0u, l[m][0], 2);
        l[m][1] += __shfl_xor_sync(~0u, l[m][1], 1);
        l[m][1] += __shfl_xor_sync(~0u, l[m][1], 2);
    }

    __syncthreads();   // all warps done with QF before it becomes OX

    // cross-group combine: group 1 dumps partial O/l; group 0 sums + stores
    if (grp == 1){
        #pragma unroll
        for (int mt = 0; mt < 2; mt++){
            int r = mq*32 + mt*16 + g;
            #pragma unroll
            for (int ntd = 0; ntd < 8; ntd++){
                int cw = ntd*8 + (tt << 1);
                *(float2*)&OX[r*66 + cw]     = make_float2(o[mt][ntd][0], o[mt][ntd][1]);
                *(float2*)&OX[(r+8)*66 + cw] = make_float2(o[mt][ntd][2], o[mt][ntd][3]);
            }
            if (tt == 0){ LX[r] = l[mt][0]; LX[r+8] = l[mt][1]; }
        }
    }
    __syncthreads();
    if (grp == 0){
        #pragma unroll
        for (int mt = 0; mt < 2; mt++){
            int r = mq*32 + mt*16 + g;
            float ia = 1.f / (l[mt][0] + LX[r]);
            float ib = 1.f / (l[mt][1] + LX[r+8]);
            #pragma unroll
            for (int ntd = 0; ntd < 8; ntd++){
                int cw = ntd*8 + (tt << 1);
                float2 pa = *(const float2*)&OX[r*66 + cw];
                float2 pb = *(const float2*)&OX[(r+8)*66 + cw];
                int col = h*64 + cw;
                *(float2*)(out + (size_t)(qbase + r) * DM + col) =
                    make_float2((o[mt][ntd][0] + pa.x) * ia, (o[mt][ntd][1] + pa.y) * ia);
                *(float2*)(out + (size_t)(qbase + r + 8) * DM + col) =
                    make_float2((o[mt][ntd][2] + pb.x) * ib, (o[mt][ntd][3] + pb.y) * ib);
            }
        }
    }
}

// ---------------------------------------------------------------------------
extern "C" void kernel_launch(void* const* d_in, const int* in_sizes, int n_in,
                              void* d_out, int out_size)
{
    const float* query = (const float*)d_in[0];
    const float* Wq    = (const float*)d_in[1];
    const float* bq    = (const float*)d_in[2];
    const float* Wk    = (const float*)d_in[3];
    const float* bk    = (const float*)d_in[4];
    const float* Wv    = (const float*)d_in[5];
    const float* bv    = (const float*)d_in[6];
    const float* Wo    = (const float*)d_in[7];
    const float* bo    = (const float*)d_in[8];
    float* out = (float*)d_out;

    float *qb, *kb, *vb, *ab;
    cudaGetSymbolAddress((void**)&qb, g_q);
    cudaGetSymbolAddress((void**)&kb, g_k);
    cudaGetSymbolAddress((void**)&vb, g_v);
    cudaGetSymbolAddress((void**)&ab, g_attn);

    const int GS128 = 2*(32*ATS) + 2*(64*BTS);   // 67584
    const int GS64  = 2*(32*ATS) + 2*(32*BTS);   // 50688
    const int ASMEM = 33792 + 512 + 4*16384;     // 99840

    cudaFuncSetAttribute((const void*)gemm_mma<128,0>, cudaFuncAttributeMaxDynamicSharedMemorySize, GS128);
    cudaFuncSetAttribute((const void*)gemm_mma<64,1>,  cudaFuncAttributeMaxDynamicSharedMemorySize, GS64);
    cudaFuncSetAttribute((const void*)gemm_mma<64,2>,  cudaFuncAttributeMaxDynamicSharedMemorySize, GS64);
    cudaFuncSetAttribute((const void*)attn_mma,        cudaFuncAttributeMaxDynamicSharedMemorySize, ASMEM);

    // K/V projections -> tf32 frag arrays (attention-ready layout)
    gemm_mma<64,1><<<dim3(1, 32), 256, GS64 >>>(query, Wk, bk, kb, MROWS, 64, DM);
    gemm_mma<64,2><<<dim3(1, 32), 256, GS64 >>>(query, Wv, bv, vb, MROWS, 64, DM);
    gemm_mma<128,0><<<dim3(8, 32), 256, GS128>>>(query, Wq, bq, qb, MROWS, DM, DM);

    attn_mma<<<512, 256, ASMEM>>>(qb, kb, vb, ab);

    gemm_mma<128,0><<<dim3(8, 32), 256, GS128>>>(ab, Wo, bo, out, MROWS, DM, DM);
}

// round 14
// speedup vs baseline: 1.7765x; 1.1110x over previous
#include <cuda_runtime.h>
#include <cstdint>

#define TT 2048
#define DM 1024
#define MROWS 4096

// Scratch (no cudaMalloc allowed)
__device__ uint32_t g_af[MROWS*DM];      // query in A-frag tf32 layout
__device__ uint32_t g_qf[MROWS*DM];      // Q-proj output, A-frag (pre-scaled 1/8)
__device__ uint32_t g_kf[MROWS*64];      // K-proj output, K-B-frag
__device__ uint32_t g_vf[MROWS*64];      // V-proj output, V-B-frag (key-permuted)
__device__ uint32_t g_of[MROWS*DM];      // attention output, A-frag
__device__ uint32_t g_wq[DM*DM];         // formatted weights (B-frag)
__device__ uint32_t g_wo[DM*DM];
__device__ uint32_t g_wk[DM*64];
__device__ uint32_t g_wv[DM*64];

static __device__ __forceinline__ uint32_t f2tf32(float x){
    uint32_t u; asm("cvt.rn.tf32.f32 %0, %1;" : "=r"(u) : "f"(x)); return u;
}
static __device__ __forceinline__ void mma8(float* c, const uint32_t* a, const uint32_t* b){
    asm volatile("mma.sync.aligned.m16n8k8.row.col.f32.tf32.tf32.f32 "
        "{%0,%1,%2,%3}, {%4,%5,%6,%7}, {%8,%9}, {%0,%1,%2,%3};"
        : "+f"(c[0]),"+f"(c[1]),"+f"(c[2]),"+f"(c[3])
        : "r"(a[0]),"r"(a[1]),"r"(a[2]),"r"(a[3]), "r"(b[0]),"r"(b[1]));
}
static __device__ __forceinline__ void cp16(uint32_t dst_smem, const void* src){
    asm volatile("cp.async.cg.shared.global [%0], [%1], 16;" :: "r"(dst_smem), "l"(src));
}
static __device__ __forceinline__ uint32_t smem_u32(const void* p){
    uint32_t a;
    asm("{ .reg .u64 t; cvta.to.shared.u64 t, %1; cvt.u32.u64 %0, t; }" : "=r"(a) : "l"(p));
    return a;
}

// A-frag word for element (row,col) within its [16 x 8] tile (128 words):
//   word = ((r&7)*4 + (c&3))*4 + ((c&7)>>2)*2 + ((r&15)>>3)
static __device__ __forceinline__ int afrag_word(int r, int c){
    return (((r & 7) << 2) + (c & 3)) * 4 + (((c & 7) >> 2) << 1) + ((r & 15) >> 3);
}

// ---------------------------------------------------------------------------
// Format kernels (run once per launch; bandwidth-trivial)
// ---------------------------------------------------------------------------
__global__ __launch_bounds__(256) void fmt_a(const float* __restrict__ A, uint32_t* __restrict__ out){
    int i = (blockIdx.x * 256 + threadIdx.x) * 4;        // K = 1024 fixed
    int r = i >> 10, k0 = i & 1023;
    float4 a = *(const float4*)(A + (size_t)r * 1024 + k0);
    float v[4] = {a.x, a.y, a.z, a.w};
    #pragma unroll
    for (int j = 0; j < 4; j++){
        int k = k0 + j;
        size_t t = (size_t)(r >> 4) * 128 + (k >> 3);
        out[t * 128 + afrag_word(r, k)] = f2tf32(v[j]);
    }
}
// B-frag: tile (k>>3)*(N/8) + (n>>3), word = ((n&7)*4 + (k&3))*2 + ((k&7)>>2)
__global__ __launch_bounds__(256) void fmt_w(const float* __restrict__ W, uint32_t* __restrict__ out, int N){
    int i = (blockIdx.x * 256 + threadIdx.x) * 4;
    int k = i / N, n0 = i % N;
    float4 w = *(const float4*)(W + (size_t)k * N + n0);
    float v[4] = {w.x, w.y, w.z, w.w};
    int NG = N >> 3, kk = k & 7;
    #pragma unroll
    for (int j = 0; j < 4; j++){
        int n = n0 + j;
        size_t t = (size_t)(k >> 3) * NG + (n >> 3);
        out[t * 64 + (((n & 7) << 2) + (kk & 3)) * 2 + (kk >> 2)] = f2tf32(v[j]);
    }
}

// ---------------------------------------------------------------------------
// GEMM v3: both operands pre-formatted, pulled with cp.async. BK=32.
// Block 128 x NT, 256 threads, warp grid 2x4, warp tile 64 x NT/4.
// EPI=0: plain fp32 C + bias.  EPI=1: K-B-frag.  EPI=2: V-B-frag (permuted).
// EPI=3: A-frag with (acc+bias)*oscale.
// ---------------------------------------------------------------------------
template<int NT, int EPI>
__global__ __launch_bounds__(256, 2) void gemm_mma(
    const uint32_t* __restrict__ Af, const uint32_t* __restrict__ Wf,
    const float* __restrict__ bias, float* __restrict__ C,
    int M, int N, int K, float oscale)
{
    extern __shared__ char smem[];
    constexpr int WNT = NT / 32, NTT = NT / 8;
    constexpr int ABUF = 16384, BBUF = NT * 128;
    constexpr int BF4_KS = NTT * 16;            // B float4s per k-tile slice
    const int tid = threadIdx.x, lane = tid & 31, wid = tid >> 5;
    const int wm = wid >> 2, wn = wid & 3;
    const int bm = blockIdx.y * 128, bn = blockIdx.x * NT;
    const int NC = K >> 5, K8 = K >> 3, NG = N >> 3;
    const uint32_t sb = smem_u32(smem);

    auto cpa = [&](int c, int buf){
        uint32_t ad = sb + buf * ABUF;
        uint32_t bd = sb + 2 * ABUF + buf * BBUF;
        #pragma unroll
        for (int j = 0; j < 4; j++){
            int i = tid + (j << 8);               // 32 A-tiles x 32 float4
            int t = i >> 5, w4 = i & 31;
            cp16(ad + t * 512 + w4 * 16,
                 Af + ((size_t)((bm >> 4) + (t >> 2)) * K8 + (c << 2) + (t & 3)) * 128 + w4 * 4);
        }
        #pragma unroll
        for (int j = 0; j < NT / 32; j++){        // B: 4 k-slices, each contiguous
            int i = tid + (j << 8);
            int ks = i / BF4_KS, off = i % BF4_KS;
            cp16(bd + i * 16,
                 Wf + ((size_t)((c << 2) + ks) * NG + (bn >> 3)) * 64 + off * 4);
        }
        asm volatile("cp.async.commit_group;" ::: "memory");
    };

    float acc[4][WNT][4] = {};
    auto comp = [&](int buf){
        const char* as = smem + buf * ABUF;
        const char* bs = smem + 2 * ABUF + buf * BBUF;
        #pragma unroll
        for (int ks = 0; ks < 4; ks++){
            uint4 af[4]; uint2 bf[WNT];
            #pragma unroll
            for (int mt = 0; mt < 4; mt++)
                af[mt] = *(const uint4*)(as + ((wm*4 + mt)*4 + ks) * 512 + lane * 16);
            #pragma unroll
            for (int nt = 0; nt < WNT; nt++)
                bf[nt] = *(const uint2*)(bs + (ks*NTT + wn*WNT + nt) * 256 + lane * 8);
            #pragma unroll
            for (int mt = 0; mt < 4; mt++)
                #pragma unroll
                for (int nt = 0; nt < WNT; nt++)
                    mma8(acc[mt][nt], (const uint32_t*)&af[mt], (const uint32_t*)&bf[nt]);
        }
    };

    cpa(0, 0);
    asm volatile("cp.async.wait_group 0;" ::: "memory");
    __syncthreads();
    for (int c = 0; c < NC; c++){
        if (c + 1 < NC) cpa(c + 1, (c + 1) & 1);
        comp(c & 1);
        if (c + 1 < NC) asm volatile("cp.async.wait_group 0;" ::: "memory");
        __syncthreads();
    }

    const int g = lane >> 2, tt = lane & 3;
    uint32_t* Cf = (uint32_t*)C;
    auto put_kv = [&](int key, int d, float val){
        int bI = key >> 11, rk = key & 2047;
        int base = (((bI*32 + (rk >> 6))*8 + ((rk >> 3) & 7))*8 + (d >> 3)) * 64;
        int kk = rk & 7;
        int off;
        if (EPI == 1) off = (kk*4 + (d & 3))*2 + ((d & 7) >> 2);
        else { int kn = (kk >> 1) + ((kk & 1) << 2); off = ((d & 7)*4 + (kn & 3))*2 + (kn >> 2); }
        Cf[base + off] = f2tf32(val);
    };
    auto put_a = [&](int row, int col, float val){
        size_t t = (size_t)(row >> 4) * (size_t)NG + (col >> 3);
        Cf[t * 128 + afrag_word(row, col)] = f2tf32(val * oscale);
    };

    #pragma unroll
    for (int mt = 0; mt < 4; mt++){
        int row = bm + wm*64 + mt*16 + g;
        #pragma unroll
        for (int nt = 0; nt < WNT; nt++){
            int col = bn + (wn*WNT + nt)*8 + (tt << 1);
            float b0 = bias[col], b1 = bias[col + 1];
            float v00 = acc[mt][nt][0] + b0, v01 = acc[mt][nt][1] + b1;
            float v10 = acc[mt][nt][2] + b0, v11 = acc[mt][nt][3] + b1;
            if (EPI == 0){
                *(float2*)(C + (size_t)row * N + col)       = make_float2(v00, v01);
                *(float2*)(C + (size_t)(row + 8) * N + col) = make_float2(v10, v11);
            } else if (EPI == 3){
                put_a(row,     col, v00); put_a(row,     col + 1, v01);
                put_a(row + 8, col, v10); put_a(row + 8, col + 1, v11);
            } else {
                put_kv(row,     col, v00); put_kv(row,     col + 1, v01);
                put_kv(row + 8, col, v10); put_kv(row + 8, col + 1, v11);
            }
        }
    }
}

// ---------------------------------------------------------------------------
// mma.sync flash-MQA v6: everything pre-formatted. Q A-frags + K/V B-frags
// pulled with cp.async; zero cvt/scatter in staging; one barrier per chunk.
// Warp owns m=32; keys split across 2 warp-groups; P stays in registers.
// Epilogue writes O as global A-frag array (O-proj input).
// SMEM: QF 33792(32768 used; OX overlay) | LX 512 | KF/VF 4x16384 = 99840.
// ---------------------------------------------------------------------------
__global__ __launch_bounds__(256, 2) void attn_mma(
    const uint32_t* __restrict__ qf, const uint32_t* __restrict__ kfrag,
    const uint32_t* __restrict__ vfrag, uint32_t* __restrict__ ofrag)
{
    extern __shared__ char smem[];
    char* QF = smem;                       // 64 A-tiles x 512B (32768 used)
    float* OX = (float*)smem;              // [128][66] exchange (after loop)
    float* LX = (float*)(smem + 33792);    // [128]
    char* KB  = smem + 34304;              // KF0|KF1|VF0|VF1, 16384 each

    const int tid = threadIdx.x, lane = tid & 31, wid = tid >> 5;
    const int g = lane >> 2, tt = lane & 3;
    const int grp = wid >> 2;              // key half
    const int mq  = wid & 3;               // row quarter (32 rows)
    const int bi = blockIdx.x;
    const int qt = bi & 15, h = (bi >> 4) & 15, b = bi >> 8;
    const int qbase = b * TT + qt * 128, qb16 = qbase >> 4;

    const uint32_t QFu = smem_u32(QF);
    const uint32_t KBu = smem_u32(KB);

    auto cpkv = [&](int c, int buf){
        const uint32_t* ks = kfrag + (size_t)(b*32 + c) * 4096;
        const uint32_t* vs = vfrag + (size_t)(b*32 + c) * 4096;
        uint32_t kd = KBu + buf * 16384;
        uint32_t vd = KBu + 32768 + buf * 16384;
        #pragma unroll
        for (int j = 0; j < 4; j++){
            int idx = tid + (j << 8);
            cp16(kd + idx * 16, ks + idx * 4);
            cp16(vd + idx * 16, vs + idx * 4);
        }
        asm volatile("cp.async.commit_group;" ::: "memory");
    };

    // Q: 64 A-tiles (8 row-tiles x 8 d-tiles), pre-scaled in Q-proj epilogue
    #pragma unroll
    for (int j = 0; j < 8; j++){
        int i = tid + (j << 8);
        int t = i >> 5, w4 = i & 31;
        cp16(QFu + t * 512 + w4 * 16,
             qf + ((size_t)(qb16 + (t >> 3)) * 128 + h*8 + (t & 7)) * 128 + w4 * 4);
    }
    cpkv(0, 0);
    asm volatile("cp.async.wait_group 0;" ::: "memory");
    __syncthreads();

    float o[2][8][4] = {};
    float l[2][2] = {};

    for (int c = 0; c < 32; c++){
        if (c + 1 < 32) cpkv(c + 1, (c + 1) & 1);   // overlaps compute

        const char* KF = KB + (c & 1) * 16384;
        const char* VF = KB + 32768 + (c & 1) * 16384;

        // GEMM1: S(32 x 32 keys) = Q * K^T
        float s[2][4][4] = {};
        #pragma unroll
        for (int ks = 0; ks < 8; ks++){
            uint4 af0 = *(const uint4*)(QF + ((mq*2 + 0)*8 + ks) * 512 + lane * 16);
            uint4 af1 = *(const uint4*)(QF + ((mq*2 + 1)*8 + ks) * 512 + lane * 16);
            #pragma unroll
            for (int nt = 0; nt < 4; nt++){
                uint2 bf = *(const uint2*)(KF + (((grp*4 + nt)*8 + ks) << 8) + lane * 8);
                mma8(s[0][nt], (const uint32_t*)&af0, (const uint32_t*)&bf);
                mma8(s[1][nt], (const uint32_t*)&af1, (const uint32_t*)&bf);
            }
        }

        // exp (tf32-rounded so l matches GEMM2 exactly) + partial row sums
        #pragma unroll
        for (int m = 0; m < 2; m++)
            #pragma unroll
            for (int nt = 0; nt < 4; nt++){
                #pragma unroll
                for (int e = 0; e < 4; e++)
                    s[m][nt][e] = __uint_as_float(f2tf32(__expf(s[m][nt][e])));
                l[m][0] += s[m][nt][0] + s[m][nt][1];
                l[m][1] += s[m][nt][2] + s[m][nt][3];
            }

        // GEMM2: O += P * V ; P from registers (C-frag -> A-frag reorder)
        #pragma unroll
        for (int ksk = 0; ksk < 4; ksk++){
            uint32_t a0[4] = {__float_as_uint(s[0][ksk][0]), __float_as_uint(s[0][ksk][2]),
                              __float_as_uint(s[0][ksk][1]), __float_as_uint(s[0][ksk][3])};
            uint32_t a1[4] = {__float_as_uint(s[1][ksk][0]), __float_as_uint(s[1][ksk][2]),
                              __float_as_uint(s[1][ksk][1]), __float_as_uint(s[1][ksk][3])};
            #pragma unroll
            for (int ntd = 0; ntd < 8; ntd++){
                uint2 bf = *(const uint2*)(VF + (((grp*4 + ksk)*8 + ntd) << 8) + lane * 8);
                mma8(o[0][ntd], a0, (const uint32_t*)&bf);
                mma8(o[1][ntd], a1, (const uint32_t*)&bf);
            }
        }

        if (c + 1 < 32)
            asm volatile("cp.async.wait_group 0;" ::: "memory");
        __syncthreads();
    }

    // quad reduction of partial row sums
    #pragma unroll
    for (int m = 0; m < 2; m++){
        l[m][0] += __shfl_xor_sync(~0u, l[m][0], 1);
        l[m][0] += __shfl_xor_sync(~0u, l[m][0], 2);
        l[m][1] += __shfl_xor_sync(~0u, l[m][1], 1);
        l[m][1] += __shfl_xor_sync(~0u, l[m][1], 2);
    }

    __syncthreads();   // all warps done with QF before it becomes OX

    if (grp == 1){
        #pragma unroll
        for (int mt = 0; mt < 2; mt++){
            int r = mq*32 + mt*16 + g;
            #pragma unroll
            for (int ntd = 0; ntd < 8; ntd++){
                int cw = ntd*8 + (tt << 1);
                *(float2*)&OX[r*66 + cw]     = make_float2(o[mt][ntd][0], o[mt][ntd][1]);
                *(float2*)&OX[(r+8)*66 + cw] = make_float2(o[mt][ntd][2], o[mt][ntd][3]);
            }
            if (tt == 0){ LX[r] = l[mt][0]; LX[r+8] = l[mt][1]; }
        }
    }
    __syncthreads();
    if (grp == 0){
        #pragma unroll
        for (int mt = 0; mt < 2; mt++){
            int r = mq*32 + mt*16 + g;
            float ia = 1.f / (l[mt][0] + LX[r]);
            float ib = 1.f / (l[mt][1] + LX[r+8]);
            int row = qbase + r;
            #pragma unroll
            for (int ntd = 0; ntd < 8; ntd++){
                int cw = ntd*8 + (tt << 1);
                float2 pa = *(const float2*)&OX[r*66 + cw];
                float2 pb = *(const float2*)&OX[(r+8)*66 + cw];
                int col = h*64 + cw;
                size_t tb = ((size_t)(row >> 4) * 128 + (col >> 3)) * 128;
                ofrag[tb + afrag_word(row,     col)]     = f2tf32((o[mt][ntd][0] + pa.x) * ia);
                ofrag[tb + afrag_word(row,     col + 1)] = f2tf32((o[mt][ntd][1] + pa.y) * ia);
                ofrag[tb + afrag_word(row + 8, col)]     = f2tf32((o[mt][ntd][2] + pb.x) * ib);
                ofrag[tb + afrag_word(row + 8, col + 1)] = f2tf32((o[mt][ntd][3] + pb.y) * ib);
            }
        }
    }
}

// ---------------------------------------------------------------------------
extern "C" void kernel_launch(void* const* d_in, const int* in_sizes, int n_in,
                              void* d_out, int out_size)
{
    const float* query = (const float*)d_in[0];
    const float* Wq    = (const float*)d_in[1];
    const float* bq    = (const float*)d_in[2];
    const float* Wk    = (const float*)d_in[3];
    const float* bk    = (const float*)d_in[4];
    const float* Wv    = (const float*)d_in[5];
    const float* bv    = (const float*)d_in[6];
    const float* Wo    = (const float*)d_in[7];
    const float* bo    = (const float*)d_in[8];
    float* out = (float*)d_out;

    uint32_t *af, *qfp, *kf, *vf, *of, *wq, *wo, *wk, *wv;
    cudaGetSymbolAddress((void**)&af,  g_af);
    cudaGetSymbolAddress((void**)&qfp, g_qf);
    cudaGetSymbolAddress((void**)&kf,  g_kf);
    cudaGetSymbolAddress((void**)&vf,  g_vf);
    cudaGetSymbolAddress((void**)&of,  g_of);
    cudaGetSymbolAddress((void**)&wq,  g_wq);
    cudaGetSymbolAddress((void**)&wo,  g_wo);
    cudaGetSymbolAddress((void**)&wk,  g_wk);
    cudaGetSymbolAddress((void**)&wv,  g_wv);

    const int GS128 = 2*16384 + 2*(128*128);   // 65536
    const int GS64  = 2*16384 + 2*(64*128);    // 49152
    const int ASMEM = 33792 + 512 + 4*16384;   // 99840

    cudaFuncSetAttribute((const void*)gemm_mma<128,0>, cudaFuncAttributeMaxDynamicSharedMemorySize, GS128);
    cudaFuncSetAttribute((const void*)gemm_mma<128,3>, cudaFuncAttributeMaxDynamicSharedMemorySize, GS128);
    cudaFuncSetAttribute((const void*)gemm_mma<64,1>,  cudaFuncAttributeMaxDynamicSharedMemorySize, GS64);
    cudaFuncSetAttribute((const void*)gemm_mma<64,2>,  cudaFuncAttributeMaxDynamicSharedMemorySize, GS64);
    cudaFuncSetAttribute((const void*)attn_mma,        cudaFuncAttributeMaxDynamicSharedMemorySize, ASMEM);

    // Format inputs (once): query -> A-frag, weights -> B-frag
    fmt_a<<<4096, 256>>>(query, af);
    fmt_w<<<1024, 256>>>(Wq, wq, DM);
    fmt_w<<<64,   256>>>(Wk, wk, 64);
    fmt_w<<<64,   256>>>(Wv, wv, 64);
    fmt_w<<<1024, 256>>>(Wo, wo, DM);

    // Projections (pure-copy GEMMs)
    gemm_mma<64,1> <<<dim3(1, 32), 256, GS64 >>>(af, wk, bk, (float*)kf,  MROWS, 64, DM, 1.f);
    gemm_mma<64,2> <<<dim3(1, 32), 256, GS64 >>>(af, wv, bv, (float*)vf,  MROWS, 64, DM, 1.f);
    gemm_mma<128,3><<<dim3(8, 32), 256, GS128>>>(af, wq, bq, (float*)qfp, MROWS, DM, DM, 0.125f);

    attn_mma<<<512, 256, ASMEM>>>(qfp, kf, vf, of);

    gemm_mma<128,0><<<dim3(8, 32), 256, GS128>>>(of, wo, bo, out, MROWS, DM, DM, 1.f);
}

// round 17
// speedup vs baseline: 1.8653x; 1.0500x over previous
#include <cuda_runtime.h>
#include <cstdint>

#define TT 2048
#define DM 1024
#define MROWS 4096

// Scratch (no cudaMalloc allowed)
__device__ uint32_t g_af[MROWS*DM];      // query in A-frag tf32 layout
__device__ uint32_t g_qf[MROWS*DM];      // Q-proj output, A-frag (pre-scaled 1/8)
__device__ uint32_t g_kf[MROWS*64];      // K-proj output, K-B-frag
__device__ uint32_t g_vf[MROWS*64];      // V-proj output, V-B-frag (key-permuted)
__device__ uint32_t g_of[MROWS*DM];      // attention output, A-frag
__device__ uint32_t g_wq[DM*DM];         // formatted weights (B-frag)
__device__ uint32_t g_wo[DM*DM];
__device__ uint32_t g_wk[DM*64];
__device__ uint32_t g_wv[DM*64];

static __device__ __forceinline__ uint32_t f2tf32(float x){
    uint32_t u; asm("cvt.rn.tf32.f32 %0, %1;" : "=r"(u) : "f"(x)); return u;
}
static __device__ __forceinline__ void mma8(float* c, const uint32_t* a, const uint32_t* b){
    asm volatile("mma.sync.aligned.m16n8k8.row.col.f32.tf32.tf32.f32 "
        "{%0,%1,%2,%3}, {%4,%5,%6,%7}, {%8,%9}, {%0,%1,%2,%3};"
        : "+f"(c[0]),"+f"(c[1]),"+f"(c[2]),"+f"(c[3])
        : "r"(a[0]),"r"(a[1]),"r"(a[2]),"r"(a[3]), "r"(b[0]),"r"(b[1]));
}
static __device__ __forceinline__ void cp16(uint32_t dst_smem, const void* src){
    asm volatile("cp.async.cg.shared.global [%0], [%1], 16;" :: "r"(dst_smem), "l"(src));
}
static __device__ __forceinline__ uint32_t smem_u32(const void* p){
    uint32_t a;
    asm("{ .reg .u64 t; cvta.to.shared.u64 t, %1; cvt.u32.u64 %0, t; }" : "=r"(a) : "l"(p));
    return a;
}
#define CP_COMMIT()  asm volatile("cp.async.commit_group;" ::: "memory")
#define CP_WAIT(n)   asm volatile("cp.async.wait_group %0;" :: "n"(n) : "memory")
#define BAR_G(id)    asm volatile("bar.sync %0, 128;" :: "r"(id) : "memory")

// A-frag word for element (row,col) within its [16 x 8] tile (128 words)
static __device__ __forceinline__ int afrag_word(int r, int c){
    return (((r & 7) << 2) + (c & 3)) * 4 + (((c & 7) >> 2) << 1) + ((r & 15) >> 3);
}

// ---------------------------------------------------------------------------
// Fused format kernel: query -> A-frag; Wq/Wk/Wv/Wo -> B-frag. One launch.
// Blocks: [0,4096) A | [4096,5120) Wq | [5120,5184) Wk | [5184,5248) Wv |
//         [5248,6272) Wo
// ---------------------------------------------------------------------------
static __device__ __forceinline__ void fmt_w_body(
    const float* __restrict__ W, uint32_t* __restrict__ out, int N, int i)
{
    int k = i / N, n0 = i % N;
    float4 w = *(const float4*)(W + (size_t)k * N + n0);
    float v[4] = {w.x, w.y, w.z, w.w};
    int NG = N >> 3, kk = k & 7;
    #pragma unroll
    for (int j = 0; j < 4; j++){
        int n = n0 + j;
        size_t t = (size_t)(k >> 3) * NG + (n >> 3);
        out[t * 64 + (((n & 7) << 2) + (kk & 3)) * 2 + (kk >> 2)] = f2tf32(v[j]);
    }
}
__global__ __launch_bounds__(256) void fmt_all(
    const float* __restrict__ query,
    const float* __restrict__ Wq, const float* __restrict__ Wk,
    const float* __restrict__ Wv, const float* __restrict__ Wo,
    uint32_t* af, uint32_t* wq, uint32_t* wk, uint32_t* wv, uint32_t* wo)
{
    int bid = blockIdx.x, tid = threadIdx.x;
    if (bid < 4096){
        int i = (bid * 256 + tid) * 4;           // K = 1024
        int r = i >> 10, k0 = i & 1023;
        float4 a = *(const float4*)(query + (size_t)r * 1024 + k0);
        float v[4] = {a.x, a.y, a.z, a.w};
        #pragma unroll
        for (int j = 0; j < 4; j++){
            int k = k0 + j;
            size_t t = (size_t)(r >> 4) * 128 + (k >> 3);
            af[t * 128 + afrag_word(r, k)] = f2tf32(v[j]);
        }
    }
    else if (bid < 5120) fmt_w_body(Wq, wq, DM, ((bid - 4096) * 256 + tid) * 4);
    else if (bid < 5184) fmt_w_body(Wk, wk, 64, ((bid - 5120) * 256 + tid) * 4);
    else if (bid < 5248) fmt_w_body(Wv, wv, 64, ((bid - 5184) * 256 + tid) * 4);
    else                 fmt_w_body(Wo, wo, DM, ((bid - 5248) * 256 + tid) * 4);
}

// ---------------------------------------------------------------------------
// GEMM (NT=128), 3-stage cp.async pipeline. EPI=0: fp32 C + bias.
// EPI=3: A-frag out, (acc+bias)*oscale. Block 128x128, BK=32, 256 thr.
// SMEM: 3 x 16KB A + 3 x 16KB B = 98304.
// ---------------------------------------------------------------------------
template<int EPI>
__global__ __launch_bounds__(256, 2) void gemm_mma(
    const uint32_t* __restrict__ Af, const uint32_t* __restrict__ Wf,
    const float* __restrict__ bias, float* __restrict__ C,
    int M, int N, int K, float oscale)
{
    extern __shared__ char smem[];
    constexpr int NT = 128, WNT = 4, NTT = 16;
    const int tid = threadIdx.x, lane = tid & 31, wid = tid >> 5;
    const int wm = wid >> 2, wn = wid & 3;
    const int bm = blockIdx.y * 128, bn = blockIdx.x * NT;
    const int NC = K >> 5, K8 = K >> 3, NG = N >> 3;
    const uint32_t sb = smem_u32(smem);

    auto cpa = [&](int c, int buf){
        uint32_t ad = sb + buf * 16384;
        uint32_t bd = sb + 3 * 16384 + buf * 16384;
        #pragma unroll
        for (int j = 0; j < 4; j++){
            int i = tid + (j << 8);               // 32 A-tiles x 32 float4
            int t = i >> 5, w4 = i & 31;
            cp16(ad + t * 512 + w4 * 16,
                 Af + ((size_t)((bm >> 4) + (t >> 2)) * K8 + (c << 2) + (t & 3)) * 128 + w4 * 4);
        }
        #pragma unroll
        for (int j = 0; j < 4; j++){              // B: 4 k-slices, each contiguous
            int i = tid + (j << 8);
            int ks = i >> 8, off = i & 255;       // BF4 per slice = 16*16 = 256
            cp16(bd + i * 16,
                 Wf + ((size_t)((c << 2) + ks) * NG + (bn >> 3)) * 64 + off * 4);
        }
        CP_COMMIT();
    };

    float acc[4][WNT][4] = {};
    auto comp = [&](int buf){
        const char* as = smem + buf * 16384;
        const char* bs = smem + 3 * 16384 + buf * 16384;
        #pragma unroll
        for (int ks = 0; ks < 4; ks++){
            uint4 af[4]; uint2 bf[WNT];
            #pragma unroll
            for (int mt = 0; mt < 4; mt++)
                af[mt] = *(const uint4*)(as + ((wm*4 + mt)*4 + ks) * 512 + lane * 16);
            #pragma unroll
            for (int nt = 0; nt < WNT; nt++)
                bf[nt] = *(const uint2*)(bs + (ks*NTT + wn*WNT + nt) * 256 + lane * 8);
            #pragma unroll
            for (int mt = 0; mt < 4; mt++)
                #pragma unroll
                for (int nt = 0; nt < WNT; nt++)
                    mma8(acc[mt][nt], (const uint32_t*)&af[mt], (const uint32_t*)&bf[nt]);
        }
    };

    cpa(0, 0); cpa(1, 1);
    for (int c = 0; c < NC; c++){
        if (c + 1 < NC) CP_WAIT(1); else CP_WAIT(0);
        __syncthreads();
        if (c + 2 < NC) cpa(c + 2, (c + 2) % 3);
        comp(c % 3);
    }

    const int g = lane >> 2, tt = lane & 3;
    uint32_t* Cf = (uint32_t*)C;
    auto put_a = [&](int row, int col, float val){
        size_t t = (size_t)(row >> 4) * (size_t)NG + (col >> 3);
        Cf[t * 128 + afrag_word(row, col)] = f2tf32(val * oscale);
    };

    #pragma unroll
    for (int mt = 0; mt < 4; mt++){
        int row = bm + wm*64 + mt*16 + g;
        #pragma unroll
        for (int nt = 0; nt < WNT; nt++){
            int col = bn + (wn*WNT + nt)*8 + (tt << 1);
            float b0 = bias[col], b1 = bias[col + 1];
            float v00 = acc[mt][nt][0] + b0, v01 = acc[mt][nt][1] + b1;
            float v10 = acc[mt][nt][2] + b0, v11 = acc[mt][nt][3] + b1;
            if (EPI == 0){
                *(float2*)(C + (size_t)row * N + col)       = make_float2(v00, v01);
                *(float2*)(C + (size_t)(row + 8) * N + col) = make_float2(v10, v11);
            } else {
                put_a(row,     col, v00); put_a(row,     col + 1, v01);
                put_a(row + 8, col, v10); put_a(row + 8, col + 1, v11);
            }
        }
    }
}

// ---------------------------------------------------------------------------
// Fused K+V projection: grid (2, 32); blockIdx.x selects K (0) or V (1).
// NT=64, BK=32, 3-stage pipeline. SMEM: 3x16KB A + 3x8KB B = 73728.
// ---------------------------------------------------------------------------
__global__ __launch_bounds__(256, 2) void gemm_kv(
    const uint32_t* __restrict__ Af,
    const uint32_t* __restrict__ WfK, const uint32_t* __restrict__ WfV,
    const float* __restrict__ bK, const float* __restrict__ bV,
    uint32_t* __restrict__ kf, uint32_t* __restrict__ vf)
{
    extern __shared__ char smem[];
    const int tid = threadIdx.x, lane = tid & 31, wid = tid >> 5;
    const int wm = wid >> 2, wn = wid & 3;
    const int bm = blockIdx.y * 128;
    const int isV = blockIdx.x;
    const uint32_t* Wf = isV ? WfV : WfK;
    const float* bias  = isV ? bV  : bK;
    uint32_t* Cf       = isV ? vf  : kf;
    const int NC = 32, K8 = 128;
    const uint32_t sb = smem_u32(smem);

    auto cpa = [&](int c, int buf){
        uint32_t ad = sb + buf * 16384;
        uint32_t bd = sb + 3 * 16384 + buf * 8192;
        #pragma unroll
        for (int j = 0; j < 4; j++){
            int i = tid + (j << 8);
            int t = i >> 5, w4 = i & 31;
            cp16(ad + t * 512 + w4 * 16,
                 Af + ((size_t)((bm >> 4) + (t >> 2)) * K8 + (c << 2) + (t & 3)) * 128 + w4 * 4);
        }
        #pragma unroll
        for (int j = 0; j < 2; j++){              // B: 512 float4, k-slice = 512 words
            int i = tid + (j << 8);
            int ks = i >> 7, off = i & 127;
            cp16(bd + i * 16, Wf + (size_t)((c << 2) + ks) * 512 + off * 4);
        }
        CP_COMMIT();
    };

    float acc[4][2][4] = {};
    auto comp = [&](int buf){
        const char* as = smem + buf * 16384;
        const char* bs = smem + 3 * 16384 + buf * 8192;
        #pragma unroll
        for (int ks = 0; ks < 4; ks++){
            uint4 af[4]; uint2 bf[2];
            #pragma unroll
            for (int mt = 0; mt < 4; mt++)
                af[mt] = *(const uint4*)(as + ((wm*4 + mt)*4 + ks) * 512 + lane * 16);
            #pragma unroll
            for (int nt = 0; nt < 2; nt++)
                bf[nt] = *(const uint2*)(bs + (ks*8 + wn*2 + nt) * 256 + lane * 8);
            #pragma unroll
            for (int mt = 0; mt < 4; mt++)
                #pragma unroll
                for (int nt = 0; nt < 2; nt++)
                    mma8(acc[mt][nt], (const uint32_t*)&af[mt], (const uint32_t*)&bf[nt]);
        }
    };

    cpa(0, 0); cpa(1, 1);
    for (int c = 0; c < NC; c++){
        if (c + 1 < NC) CP_WAIT(1); else CP_WAIT(0);
        __syncthreads();
        if (c + 2 < NC) cpa(c + 2, (c + 2) % 3);
        comp(c % 3);
    }

    const int g = lane >> 2, tt = lane & 3;
    auto put_kv = [&](int key, int d, float val){
        int bI = key >> 11, rk = key & 2047;
        int base = (((bI*32 + (rk >> 6))*8 + ((rk >> 3) & 7))*8 + (d >> 3)) * 64;
        int kk = rk & 7;
        int off;
        if (!isV) off = (kk*4 + (d & 3))*2 + ((d & 7) >> 2);
        else { int kn = (kk >> 1) + ((kk & 1) << 2); off = ((d & 7)*4 + (kn & 3))*2 + (kn >> 2); }
        Cf[base + off] = f2tf32(val);
    };

    #pragma unroll
    for (int mt = 0; mt < 4; mt++){
        int row = bm + wm*64 + mt*16 + g;
        #pragma unroll
        for (int nt = 0; nt < 2; nt++){
            int col = (wn*2 + nt)*8 + (tt << 1);
            float b0 = bias[col], b1 = bias[col + 1];
            put_kv(row,     col,     acc[mt][nt][0] + b0);
            put_kv(row,     col + 1, acc[mt][nt][1] + b1);
            put_kv(row + 8, col,     acc[mt][nt][2] + b0);
            put_kv(row + 8, col + 1, acc[mt][nt][3] + b1);
        }
    }
}

// ---------------------------------------------------------------------------
// mma.sync flash-MQA v7: per-warp-group decoupling. Each group (4 warps)
// copies and reads ONLY its own half of KF/VF; groups synchronize with
// named barriers (ids 1,2) and free-run up to a chunk apart.
// SMEM: QF 33792(32768 used; OX overlay) | LX 512 | KF/VF 4x16384 = 99840.
// ---------------------------------------------------------------------------
__global__ __launch_bounds__(256, 2) void attn_mma(
    const uint32_t* __restrict__ qf, const uint32_t* __restrict__ kfrag,
    const uint32_t* __restrict__ vfrag, uint32_t* __restrict__ ofrag)
{
    extern __shared__ char smem[];
    char* QF = smem;                       // 64 A-tiles x 512B (32768 used)
    float* OX = (float*)smem;              // [128][66] exchange (after loop)
    float* LX = (float*)(smem + 33792);    // [128]
    char* KB  = smem + 34304;              // KF0|KF1|VF0|VF1, 16384 each

    const int tid = threadIdx.x, lane = tid & 31, wid = tid >> 5;
    const int g = lane >> 2, tt = lane & 3;
    const int grp = wid >> 2;              // key half
    const int mq  = wid & 3;               // row quarter (32 rows)
    const int lt  = tid & 127;             // thread-in-group
    const int bi = blockIdx.x;
    const int qt = bi & 15, h = (bi >> 4) & 15, b = bi >> 8;
    const int qbase = b * TT + qt * 128, qb16 = qbase >> 4;

    const uint32_t QFu = smem_u32(QF);
    const uint32_t KBu = smem_u32(KB);

    // group-scoped copy: each group pulls its own 8KB half of K and V
    auto cpkvg = [&](int c, int buf){
        const uint32_t* ks = kfrag + (size_t)(b*32 + c) * 4096 + grp * 2048;
        const uint32_t* vs = vfrag + (size_t)(b*32 + c) * 4096 + grp * 2048;
        uint32_t kd = KBu + buf * 16384 + grp * 8192;
        uint32_t vd = KBu + 32768 + buf * 16384 + grp * 8192;
        #pragma unroll
        for (int j = 0; j < 4; j++){
            int idx = lt + (j << 7);               // 512 float4 per half
            cp16(kd + idx * 16, ks + idx * 4);
            cp16(vd + idx * 16, vs + idx * 4);
        }
        CP_COMMIT();
    };

    // Q: 64 A-tiles (8 row-tiles x 8 d-tiles), pre-scaled in Q-proj epilogue
    #pragma unroll
    for (int j = 0; j < 8; j++){
        int i = tid + (j << 8);
        int t = i >> 5, w4 = i & 31;
        cp16(QFu + t * 512 + w4 * 16,
             qf + ((size_t)(qb16 + (t >> 3)) * 128 + h*8 + (t & 7)) * 128 + w4 * 4);
    }
    CP_COMMIT();
    cpkvg(0, 0);
    CP_WAIT(0);
    __syncthreads();

    float o[2][8][4] = {};
    float l[2][2] = {};

    for (int c = 0; c < 32; c++){
        if (c + 1 < 32) cpkvg(c + 1, (c + 1) & 1);   // own half only

        const char* KF = KB + (c & 1) * 16384;
        const char* VF = KB + 32768 + (c & 1) * 16384;

        // GEMM1: S(32 x 32 keys) = Q * K^T (own key half)
        float s[2][4][4] = {};
        #pragma unroll
        for (int ks = 0; ks < 8; ks++){
            uint4 af0 = *(const uint4*)(QF + ((mq*2 + 0)*8 + ks) * 512 + lane * 16);
            uint4 af1 = *(const uint4*)(QF + ((mq*2 + 1)*8 + ks) * 512 + lane * 16);
            #pragma unroll
            for (int nt = 0; nt < 4; nt++){
                uint2 bf = *(const uint2*)(KF + (((grp*4 + nt)*8 + ks) << 8) + lane * 8);
                mma8(s[0][nt], (const uint32_t*)&af0, (const uint32_t*)&bf);
                mma8(s[1][nt], (const uint32_t*)&af1, (const uint32_t*)&bf);
            }
        }

        // exp (tf32-rounded so l matches GEMM2 exactly) + partial row sums
        #pragma unroll
        for (int m = 0; m < 2; m++)
            #pragma unroll
            for (int nt = 0; nt < 4; nt++){
                #pragma unroll
                for (int e = 0; e < 4; e++)
                    s[m][nt][e] = __uint_as_float(f2tf32(__expf(s[m][nt][e])));
                l[m][0] += s[m][nt][0] + s[m][nt][1];
                l[m][1] += s[m][nt][2] + s[m][nt][3];
            }

        // GEMM2: O += P * V ; P from registers (C-frag -> A-frag reorder)
        #pragma unroll
        for (int ksk = 0; ksk < 4; ksk++){
            uint32_t a0[4] = {__float_as_uint(s[0][ksk][0]), __float_as_uint(s[0][ksk][2]),
                              __float_as_uint(s[0][ksk][1]), __float_as_uint(s[0][ksk][3])};
            uint32_t a1[4] = {__float_as_uint(s[1][ksk][0]), __float_as_uint(s[1][ksk][2]),
                              __float_as_uint(s[1][ksk][1]), __float_as_uint(s[1][ksk][3])};
            #pragma unroll
            for (int ntd = 0; ntd < 8; ntd++){
                uint2 bf = *(const uint2*)(VF + (((grp*4 + ksk)*8 + ntd) << 8) + lane * 8);
                mma8(o[0][ntd], a0, (const uint32_t*)&bf);
                mma8(o[1][ntd], a1, (const uint32_t*)&bf);
            }
        }

        if (c + 1 < 32) CP_WAIT(0);
        BAR_G(1 + grp);       // group-scoped: groups free-run vs each other
    }

    // quad reduction of partial row sums
    #pragma unroll
    for (int m = 0; m < 2; m++){
        l[m][0] += __shfl_xor_sync(~0u, l[m][0], 1);
        l[m][0] += __shfl_xor_sync(~0u, l[m][0], 2);
        l[m][1] += __shfl_xor_sync(~0u, l[m][1], 1);
        l[m][1] += __shfl_xor_sync(~0u, l[m][1], 2);
    }

    __syncthreads();   // full CTA: everyone done with QF before it becomes OX

    if (grp == 1){
        #pragma unroll
        for (int mt = 0; mt < 2; mt++){
            int r = mq*32 + mt*16 + g;
            #pragma unroll
            for (int ntd = 0; ntd < 8; ntd++){
                int cw = ntd*8 + (tt << 1);
                *(float2*)&OX[r*66 + cw]     = make_float2(o[mt][ntd][0], o[mt][ntd][1]);
                *(float2*)&OX[(r+8)*66 + cw] = make_float2(o[mt][ntd][2], o[mt][ntd][3]);
            }
            if (tt == 0){ LX[r] = l[mt][0]; LX[r+8] = l[mt][1]; }
        }
    }
    __syncthreads();
    if (grp == 0){
        #pragma unroll
        for (int mt = 0; mt < 2; mt++){
            int r = mq*32 + mt*16 + g;
            float ia = 1.f / (l[mt][0] + LX[r]);
            float ib = 1.f / (l[mt][1] + LX[r+8]);
            int row = qbase + r;
            #pragma unroll
            for (int ntd = 0; ntd < 8; ntd++){
                int cw = ntd*8 + (tt << 1);
                float2 pa = *(const float2*)&OX[r*66 + cw];
                float2 pb = *(const float2*)&OX[(r+8)*66 + cw];
                int col = h*64 + cw;
                size_t tb = ((size_t)(row >> 4) * 128 + (col >> 3)) * 128;
                ofrag[tb + afrag_word(row,     col)]     = f2tf32((o[mt][ntd][0] + pa.x) * ia);
                ofrag[tb + afrag_word(row,     col + 1)] = f2tf32((o[mt][ntd][1] + pa.y) * ia);
                ofrag[tb + afrag_word(row + 8, col)]     = f2tf32((o[mt][ntd][2] + pb.x) * ib);
                ofrag[tb + afrag_word(row + 8, col + 1)] = f2tf32((o[mt][ntd][3] + pb.y) * ib);
            }
        }
    }
}

// ---------------------------------------------------------------------------
extern "C" void kernel_launch(void* const* d_in, const int* in_sizes, int n_in,
                              void* d_out, int out_size)
{
    const float* query = (const float*)d_in[0];
    const float* Wq    = (const float*)d_in[1];
    const float* bq    = (const float*)d_in[2];
    const float* Wk    = (const float*)d_in[3];
    const float* bk    = (const float*)d_in[4];
    const float* Wv    = (const float*)d_in[5];
    const float* bv    = (const float*)d_in[6];
    const float* Wo    = (const float*)d_in[7];
    const float* bo    = (const float*)d_in[8];
    float* out = (float*)d_out;

    uint32_t *af, *qfp, *kf, *vf, *of, *wq, *wo, *wk, *wv;
    cudaGetSymbolAddress((void**)&af,  g_af);
    cudaGetSymbolAddress((void**)&qfp, g_qf);
    cudaGetSymbolAddress((void**)&kf,  g_kf);
    cudaGetSymbolAddress((void**)&vf,  g_vf);
    cudaGetSymbolAddress((void**)&of,  g_of);
    cudaGetSymbolAddress((void**)&wq,  g_wq);
    cudaGetSymbolAddress((void**)&wo,  g_wo);
    cudaGetSymbolAddress((void**)&wk,  g_wk);
    cudaGetSymbolAddress((void**)&wv,  g_wv);

    const int GSQ   = 6 * 16384;               // 98304 (3-stage, NT=128)
    const int GSKV  = 3 * 16384 + 3 * 8192;    // 73728
    const int ASMEM = 33792 + 512 + 4*16384;   // 99840

    cudaFuncSetAttribute((const void*)gemm_mma<0>, cudaFuncAttributeMaxDynamicSharedMemorySize, GSQ);
    cudaFuncSetAttribute((const void*)gemm_mma<3>, cudaFuncAttributeMaxDynamicSharedMemorySize, GSQ);
    cudaFuncSetAttribute((const void*)gemm_kv,     cudaFuncAttributeMaxDynamicSharedMemorySize, GSKV);
    cudaFuncSetAttribute((const void*)attn_mma,    cudaFuncAttributeMaxDynamicSharedMemorySize, ASMEM);

    // Format everything in one launch
    fmt_all<<<6272, 256>>>(query, Wq, Wk, Wv, Wo, af, wq, wk, wv, wo);

    // K+V projections fused; Q projection (A-frag out, pre-scaled 1/8)
    gemm_kv<<<dim3(2, 32), 256, GSKV>>>(af, wk, wv, bk, bv, kf, vf);
    gemm_mma<3><<<dim3(8, 32), 256, GSQ>>>(af, wq, bq, (float*)qfp, MROWS, DM, DM, 0.125f);

    attn_mma<<<512, 256, ASMEM>>>(qfp, kf, vf, of);

    gemm_mma<0><<<dim3(8, 32), 256, GSQ>>>(of, wo, bo, out, MROWS, DM, DM, 1.f);
}